// round 4
// baseline (speedup 1.0000x reference)
#include <cuda_runtime.h>
#include <cstdint>

#define BATCH 16
#define NPT 2048
#define DIM 64
#define NMAT 32            // 2 * BATCH  (0..15 = x/gts, 16..31 = z)
#define ECAP 131072        // per-instance filtered-edge capacity
#define ADJCAP 262144      // per-instance CSR capacity (2*edges)
#define T_FILT 84.0f       // d^2 threshold (~32K edges/instance, deg ~31)
#define NROUNDS 12

typedef unsigned long long u64;

// Scratch (allocation-free rule: __device__ globals)
__device__ float g_D[(size_t)NMAT * NPT * NPT];   // 512 MB squared distances
__device__ float g_sq[NMAT * NPT];
__device__ u64   g_elist[NMAT][ECAP];
__device__ int   g_ecnt[NMAT];
__device__ int   g_ovf[NMAT];
__device__ int   g_deg[NMAT][NPT];
__device__ int   g_off[NMAT][NPT + 1];
__device__ int   g_fill[NMAT][NPT];
__device__ int   g_ptr[NMAT][NPT];
__device__ u64   g_adj[NMAT][ADJCAP];
__device__ int   g_comp[NMAT][NPT];
__device__ u64   g_best[NMAT][NPT];
__device__ int   g_nrec[NMAT];
__device__ int2  g_eroot[NMAT][NPT];              // MST edge at hooked-root slot
__device__ float g_partial[NMAT];

// ---------------------------------------------------------------------------
// 1. squared norms + zero per-call counters/degrees
// ---------------------------------------------------------------------------
__global__ void norms_kernel(const float* __restrict__ gts, const float* __restrict__ z) {
    int row = blockIdx.x * blockDim.x + threadIdx.x;
    if (row >= NMAT * NPT) return;
    ((int*)g_deg)[row] = 0;
    if (row < NMAT) { g_ecnt[row] = 0; g_ovf[row] = 0; g_nrec[row] = 0; }
    const float* P = (row < BATCH * NPT) ? gts : z;
    int r = (row < BATCH * NPT) ? row : row - BATCH * NPT;
    const float4* p = (const float4*)(P + (size_t)r * DIM);
    float s = 0.f;
#pragma unroll
    for (int k = 0; k < DIM / 4; k++) {
        float4 v = p[k];
        s += v.x * v.x + v.y * v.y + v.z * v.z + v.w * v.w;
    }
    g_sq[row] = s;
}

// ---------------------------------------------------------------------------
// 2. squared distances (upper-triangle tiles + transposed stores) with fused
//    edge filter (d2 < T, i < j) and per-node degree counting.
// ---------------------------------------------------------------------------
#define KS 16
__global__ void __launch_bounds__(256) dist_kernel(const float* __restrict__ gts,
                                                   const float* __restrict__ z) {
    int bi = blockIdx.y, bj = blockIdx.x;
    if (bj < bi) return;
    int bm = blockIdx.z;
    const float* P = (bm < BATCH) ? gts + (size_t)bm * NPT * DIM
                                  : z + (size_t)(bm - BATCH) * NPT * DIM;
    int i0 = bi * 128, j0 = bj * 128;
    int tid = threadIdx.x;
    int tx = tid & 15;
    int ty = tid >> 4;
    int lane = tid & 31;

    __shared__ float As[KS][132];
    __shared__ float Bs[KS][132];

    float acc[8][8] = {};

    for (int ks = 0; ks < DIM; ks += KS) {
        __syncthreads();
#pragma unroll
        for (int t = 0; t < 2; t++) {
            int idx = tid + t * 256;
            int i = idx >> 2;
            int kk = (idx & 3) * 4;
            float4 va = *(const float4*)(P + (size_t)(i0 + i) * DIM + ks + kk);
            As[kk + 0][i] = va.x; As[kk + 1][i] = va.y;
            As[kk + 2][i] = va.z; As[kk + 3][i] = va.w;
            float4 vb = *(const float4*)(P + (size_t)(j0 + i) * DIM + ks + kk);
            Bs[kk + 0][i] = vb.x; Bs[kk + 1][i] = vb.y;
            Bs[kk + 2][i] = vb.z; Bs[kk + 3][i] = vb.w;
        }
        __syncthreads();
#pragma unroll
        for (int k = 0; k < KS; k++) {
            float a[8], b[8];
            *(float4*)(a)     = *(const float4*)&As[k][ty * 8];
            *(float4*)(a + 4) = *(const float4*)&As[k][ty * 8 + 4];
            *(float4*)(b)     = *(const float4*)&Bs[k][tx * 8];
            *(float4*)(b + 4) = *(const float4*)&Bs[k][tx * 8 + 4];
#pragma unroll
            for (int r = 0; r < 8; r++)
#pragma unroll
                for (int c = 0; c < 8; c++)
                    acc[r][c] += a[r] * b[c];
        }
    }

    const float* sqb = g_sq + bm * NPT;
    float sqi[8], sqj[8];
#pragma unroll
    for (int r = 0; r < 8; r++) sqi[r] = sqb[i0 + ty * 8 + r];
#pragma unroll
    for (int c = 0; c < 8; c++) sqj[c] = sqb[j0 + tx * 8 + c];

#pragma unroll
    for (int r = 0; r < 8; r++)
#pragma unroll
        for (int c = 0; c < 8; c++)
            acc[r][c] = fmaxf(sqi[r] + sqj[c] - 2.f * acc[r][c], 0.f);

    float* Dm = g_D + (size_t)bm * NPT * NPT;
#pragma unroll
    for (int r = 0; r < 8; r++) {
        int gi = i0 + ty * 8 + r;
        float4 o0 = {acc[r][0], acc[r][1], acc[r][2], acc[r][3]};
        float4 o1 = {acc[r][4], acc[r][5], acc[r][6], acc[r][7]};
        *(float4*)&Dm[(size_t)gi * NPT + j0 + tx * 8]     = o0;
        *(float4*)&Dm[(size_t)gi * NPT + j0 + tx * 8 + 4] = o1;
    }
    if (bi != bj) {
#pragma unroll
        for (int c = 0; c < 8; c++) {
            int gj = j0 + tx * 8 + c;
            float4 o0 = {acc[0][c], acc[1][c], acc[2][c], acc[3][c]};
            float4 o1 = {acc[4][c], acc[5][c], acc[6][c], acc[7][c]};
            *(float4*)&Dm[(size_t)gj * NPT + i0 + ty * 8]     = o0;
            *(float4*)&Dm[(size_t)gj * NPT + i0 + ty * 8 + 4] = o1;
        }
    }

    // ---- fused edge filter ----
    unsigned nl = 0;
#pragma unroll
    for (int r = 0; r < 8; r++) {
        int gi = i0 + ty * 8 + r;
#pragma unroll
        for (int c = 0; c < 8; c++) {
            int gj = j0 + tx * 8 + c;
            if (gi < gj && acc[r][c] < T_FILT) nl++;
        }
    }
    unsigned pre = nl;
#pragma unroll
    for (int o = 1; o < 32; o <<= 1) {
        unsigned v = __shfl_up_sync(0xFFFFFFFFu, pre, o);
        if (lane >= (int)o) pre += v;
    }
    unsigned wtot = __shfl_sync(0xFFFFFFFFu, pre, 31);
    unsigned ex = pre - nl;
    if (wtot) {
        unsigned base = 0;
        if (lane == 31) base = (unsigned)atomicAdd(&g_ecnt[bm], (int)wtot);
        base = __shfl_sync(0xFFFFFFFFu, base, 31);
        if (base + wtot <= (unsigned)ECAP) {
            if (nl) {
                unsigned o = base + ex;
#pragma unroll
                for (int r = 0; r < 8; r++) {
                    int gi = i0 + ty * 8 + r;
#pragma unroll
                    for (int c = 0; c < 8; c++) {
                        int gj = j0 + tx * 8 + c;
                        if (gi < gj && acc[r][c] < T_FILT) {
                            g_elist[bm][o++] =
                                ((u64)__float_as_uint(acc[r][c]) << 22) |
                                ((unsigned)gi << 11) | (unsigned)gj;
                            atomicAdd(&g_deg[bm][gi], 1);
                            atomicAdd(&g_deg[bm][gj], 1);
                        }
                    }
                }
            }
        } else if (lane == 0) {
            g_ovf[bm] = 1;
        }
    }
}

// ---------------------------------------------------------------------------
// 3a. exclusive scan of degrees -> CSR offsets; init per-call MST state
// ---------------------------------------------------------------------------
__global__ void __launch_bounds__(256) offsets_kernel() {
    __shared__ int ssum[256];
    int bm = blockIdx.x, tid = threadIdx.x;
    int base = tid * 8;
    int d[8], loc[8], s = 0;
#pragma unroll
    for (int q = 0; q < 8; q++) d[q] = g_deg[bm][base + q];
#pragma unroll
    for (int q = 0; q < 8; q++) { loc[q] = s; s += d[q]; }
    ssum[tid] = s;
    __syncthreads();
    for (int o = 1; o < 256; o <<= 1) {
        int v = 0;
        if (tid >= o) v = ssum[tid - o];
        __syncthreads();
        ssum[tid] += v;
        __syncthreads();
    }
    int exbase = ssum[tid] - s;
#pragma unroll
    for (int q = 0; q < 8; q++) {
        int n = base + q;
        int o = exbase + loc[q];
        g_off[bm][n] = o;
        g_fill[bm][n] = o;
        g_ptr[bm][n] = o;
        g_comp[bm][n] = n;
        g_best[bm][n] = ~0ull;
        g_eroot[bm][n] = make_int2(-1, -1);
    }
    if (tid == 255) {
        g_off[bm][NPT] = ssum[255];
        if (ssum[255] > ADJCAP) g_ovf[bm] = 1;
    }
}

// ---------------------------------------------------------------------------
// 3b. fill CSR (both directions)
// ---------------------------------------------------------------------------
__global__ void fill_kernel() {
    int bm = blockIdx.y;
    if (g_ovf[bm]) return;
    int cnt = g_ecnt[bm];
    if (cnt > ECAP) cnt = ECAP;
    for (int e = blockIdx.x * blockDim.x + threadIdx.x; e < cnt;
         e += gridDim.x * blockDim.x) {
        u64 k = g_elist[bm][e];
        int i = (int)((k >> 11) & 2047), j = (int)(k & 2047);
        int pi = atomicAdd(&g_fill[bm][i], 1);
        g_adj[bm][pi] = k;
        int pj = atomicAdd(&g_fill[bm][j], 1);
        g_adj[bm][pj] = k;
    }
}

// ---------------------------------------------------------------------------
// 3c. sort each node's adjacency (one thread per node, insertion sort)
// ---------------------------------------------------------------------------
__global__ void sort_kernel() {
    int bm = blockIdx.y;
    if (g_ovf[bm]) return;
    int n = blockIdx.x * blockDim.x + threadIdx.x;
    int lo = g_off[bm][n], hi = g_off[bm][n + 1];
    u64* a = g_adj[bm];
    for (int p = lo + 1; p < hi; p++) {
        u64 k = a[p];
        int q = p - 1;
        while (q >= lo && a[q] > k) { a[q + 1] = a[q]; q--; }
        a[q + 1] = k;
    }
}

// ---------------------------------------------------------------------------
// 3d. per-round scan: each node advances its cursor past (permanently)
//     internal edges; first cross edge = node's min cross edge (sorted).
// ---------------------------------------------------------------------------
__global__ void scan_kernel() {
    int bm = blockIdx.y;
    if (g_ovf[bm] || g_nrec[bm] >= NPT - 1) return;
    int i = blockIdx.x * blockDim.x + threadIdx.x;
    int c = g_comp[bm][i];
    int p = g_ptr[bm][i];
    int e = g_off[bm][i + 1];
    u64 k = 0;
    bool found = false;
    while (p < e) {
        k = g_adj[bm][p];
        int a = (int)((k >> 11) & 2047), b = (int)(k & 2047);
        int o = (a == i) ? b : a;
        if (g_comp[bm][o] == c) p++;      // internal forever -> skip permanently
        else { found = true; break; }
    }
    g_ptr[bm][i] = p;
    if (found) atomicMin(&g_best[bm][c], k);
}

// ---------------------------------------------------------------------------
// 3e. per-round hook/record/pointer-jump/relabel (one block per instance)
// ---------------------------------------------------------------------------
__global__ void __launch_bounds__(256) hook_kernel() {
    __shared__ u64 sb[NPT];      // 16 KB
    __shared__ int scomp[NPT];   // 8 KB
    __shared__ int par[NPT];     // 8 KB
    __shared__ int tmp[NPT];     // 8 KB
    __shared__ int cnt;

    int bm = blockIdx.x, tid = threadIdx.x;
    if (g_ovf[bm] || g_nrec[bm] >= NPT - 1) return;

    for (int i = tid; i < NPT; i += 256) {
        sb[i] = g_best[bm][i];
        scomp[i] = g_comp[bm][i];
    }
    if (tid == 0) cnt = 0;
    __syncthreads();

    for (int c = tid; c < NPT; c += 256) {
        u64 k = sb[c];
        int p = c;
        if (k != ~0ull) {
            int a = (int)((k >> 11) & 2047), b = (int)(k & 2047);
            int ca = scomp[a], cb = scomp[b];
            p = (ca == c) ? cb : ca;
        }
        par[c] = p;
    }
    __syncthreads();

    // 2-cycle fix (total-order keys => only mutual pairs; race-safe)
    for (int c = tid; c < NPT; c += 256) {
        int p = par[c];
        if (p != c && par[p] == c && c < p) par[c] = c;
    }
    __syncthreads();

    for (int c = tid; c < NPT; c += 256) {
        if (par[c] != c) {
            u64 k = sb[c];
            g_eroot[bm][c] = make_int2((int)((k >> 11) & 2047), (int)(k & 2047));
            atomicAdd(&cnt, 1);
        }
    }
    __syncthreads();

    for (int it = 0; it < 11; it++) {
        for (int c = tid; c < NPT; c += 256) tmp[c] = par[par[c]];
        __syncthreads();
        for (int c = tid; c < NPT; c += 256) par[c] = tmp[c];
        __syncthreads();
    }

    for (int i = tid; i < NPT; i += 256) {
        g_comp[bm][i] = par[scomp[i]];
        g_best[bm][i] = ~0ull;
    }
    if (tid == 0) atomicAdd(&g_nrec[bm], cnt);
}

// ---------------------------------------------------------------------------
// 3f. exact full-matrix fallback (no-op when sparse phase completed)
// ---------------------------------------------------------------------------
__global__ void __launch_bounds__(256) fallback_kernel() {
    __shared__ int comp[NPT];
    __shared__ int parent[NPT];
    __shared__ u64 best[NPT];
    __shared__ int s_rec;

    int bm = blockIdx.x;
    int tid = threadIdx.x;
    int lane = tid & 31, wid = tid >> 5;

    if (!g_ovf[bm] && g_nrec[bm] >= NPT - 1) return;

    for (int i = tid; i < NPT; i += 256) comp[i] = g_comp[bm][i];
    if (tid == 0) s_rec = g_nrec[bm];
    __syncthreads();

    const float* Dm = g_D + (size_t)bm * NPT * NPT;
    for (int round = 0; round < 12; round++) {
        if (s_rec >= NPT - 1) break;
        for (int i = tid; i < NPT; i += 256) best[i] = ~0ull;
        __syncthreads();

        for (int i = wid; i < NPT; i += 8) {
            int ci = comp[i];
            const float4* row = (const float4*)(Dm + (size_t)i * NPT);
            u64 lb = ~0ull;
            for (int jc = lane; jc < NPT / 4; jc += 32) {
                float4 d4 = row[jc];
                float dv[4] = {d4.x, d4.y, d4.z, d4.w};
#pragma unroll
                for (int q = 0; q < 4; q++) {
                    int j = jc * 4 + q;
                    if (comp[j] != ci) {
                        int lo = i < j ? i : j, hi = i < j ? j : i;
                        u64 k = ((u64)__float_as_uint(dv[q]) << 22) |
                                ((unsigned)lo << 11) | (unsigned)hi;
                        if (k < lb) lb = k;
                    }
                }
            }
#pragma unroll
            for (int o = 16; o; o >>= 1) {
                u64 v = __shfl_down_sync(0xFFFFFFFFu, lb, o);
                if (v < lb) lb = v;
            }
            if (lane == 0 && lb != ~0ull) atomicMin(&best[ci], lb);
        }
        __syncthreads();

        for (int c = tid; c < NPT; c += 256) {
            u64 k = best[c];
            int p = c;
            if (k != ~0ull) {
                int i = (int)((k >> 11) & 2047), j = (int)(k & 2047);
                int ci = comp[i], cj = comp[j];
                p = (ci == c) ? cj : ci;
            }
            parent[c] = p;
        }
        __syncthreads();
        for (int c = tid; c < NPT; c += 256) {
            int p = parent[c];
            if (p != c && parent[p] == c && c < p) parent[c] = c;
        }
        __syncthreads();
        for (int c = tid; c < NPT; c += 256) {
            if (parent[c] != c) {
                u64 k = best[c];
                g_eroot[bm][c] = make_int2((int)((k >> 11) & 2047), (int)(k & 2047));
                atomicAdd(&s_rec, 1);
            }
        }
        __syncthreads();
        int* tmp = (int*)best;
        for (int it = 0; it < 11; it++) {
            for (int c = tid; c < NPT; c += 256) tmp[c] = parent[parent[c]];
            __syncthreads();
            for (int c = tid; c < NPT; c += 256) parent[c] = tmp[c];
            __syncthreads();
        }
        for (int i = tid; i < NPT; i += 256) comp[i] = parent[comp[i]];
        __syncthreads();
    }
}

// ---------------------------------------------------------------------------
// 4. loss
// ---------------------------------------------------------------------------
__global__ void loss_kernel() {
    int bm = blockIdx.x;
    int b = bm & (BATCH - 1);
    const float* Dx = g_D + (size_t)b * NPT * NPT;
    const float* Dz = g_D + (size_t)(BATCH + b) * NPT * NPT;

    float acc = 0.f;
    for (int s = threadIdx.x; s < NPT; s += 256) {
        int2 p = g_eroot[bm][s];
        if (p.x >= 0) {
            float dx = sqrtf(Dx[(size_t)p.x * NPT + p.y]);
            float dz = sqrtf(Dz[(size_t)p.x * NPT + p.y]);
            float t = dx - dz;
            acc += t * t;
        }
    }
    __shared__ float sm[256];
    sm[threadIdx.x] = acc;
    __syncthreads();
    for (int s = 128; s; s >>= 1) {
        if (threadIdx.x < s) sm[threadIdx.x] += sm[threadIdx.x + s];
        __syncthreads();
    }
    if (threadIdx.x == 0) g_partial[bm] = sm[0];
}

__global__ void final_kernel(float* out) {
    if (threadIdx.x == 0) {
        float s = 0.f;
        for (int i = 0; i < NMAT; i++) s += g_partial[i];
        out[0] = 0.5f * s;
    }
}

// ---------------------------------------------------------------------------
extern "C" void kernel_launch(void* const* d_in, const int* in_sizes, int n_in,
                              void* d_out, int out_size) {
    (void)in_sizes; (void)n_in; (void)out_size;
    const float* gts = (const float*)d_in[0];
    const float* z   = (const float*)d_in[1];

    norms_kernel<<<NMAT * NPT / 256, 256>>>(gts, z);

    dim3 g(NPT / 128, NPT / 128, NMAT);
    dist_kernel<<<g, 256>>>(gts, z);

    offsets_kernel<<<NMAT, 256>>>();
    fill_kernel<<<dim3(8, NMAT), 256>>>();
    sort_kernel<<<dim3(NPT / 256, NMAT), 256>>>();

    for (int r = 0; r < NROUNDS; r++) {
        scan_kernel<<<dim3(NPT / 256, NMAT), 256>>>();
        hook_kernel<<<NMAT, 256>>>();
    }
    fallback_kernel<<<NMAT, 256>>>();

    loss_kernel<<<NMAT, 256>>>();
    final_kernel<<<1, 32>>>((float*)d_out);
}

// round 5
// speedup vs baseline: 3.5695x; 3.5695x over previous
#include <cuda_runtime.h>
#include <cstdint>

#define BATCH 16
#define NPT 2048
#define DIM 64
#define NMAT 32            // 2 * BATCH  (0..15 = x/gts, 16..31 = z)
#define ECAP 131072        // per-instance filtered-edge capacity
#define T_FILT 84.0f       // d^2 threshold (~56K edges/instance)
#define NROUNDS 11

typedef unsigned long long u64;

// Scratch (allocation-free rule: __device__ globals)
__device__ float g_D[(size_t)NMAT * NPT * NPT];   // 512 MB squared distances
__device__ float g_sq[NMAT * NPT];
__device__ u64   g_ebuf[2][NMAT][ECAP];           // double-buffered edge lists
__device__ int   g_cnt[2][NMAT];
__device__ int   g_ovf[NMAT];
__device__ int   g_comp[NMAT][NPT];
__device__ u64   g_best[NMAT][NPT];
__device__ int   g_nrec[NMAT];
__device__ int2  g_eroot[NMAT][NPT];              // MST edge at hooked-root slot
__device__ float g_partial[NMAT];

// ---------------------------------------------------------------------------
// 1. squared norms + all per-call state init (65536 threads == NMAT*NPT slots)
// ---------------------------------------------------------------------------
__global__ void norms_kernel(const float* __restrict__ gts, const float* __restrict__ z) {
    int row = blockIdx.x * blockDim.x + threadIdx.x;
    if (row >= NMAT * NPT) return;
    int bm = row >> 11, n = row & (NPT - 1);
    g_comp[bm][n] = n;
    g_best[bm][n] = ~0ull;
    g_eroot[bm][n] = make_int2(-1, -1);
    if (row < NMAT) {
        g_cnt[0][row] = 0; g_cnt[1][row] = 0;
        g_ovf[row] = 0; g_nrec[row] = 0;
    }
    const float* P = (row < BATCH * NPT) ? gts : z;
    int r = (row < BATCH * NPT) ? row : row - BATCH * NPT;
    const float4* p = (const float4*)(P + (size_t)r * DIM);
    float s = 0.f;
#pragma unroll
    for (int k = 0; k < DIM / 4; k++) {
        float4 v = p[k];
        s += v.x * v.x + v.y * v.y + v.z * v.z + v.w * v.w;
    }
    g_sq[row] = s;
}

// ---------------------------------------------------------------------------
// 2. squared distances (upper-triangle tiles + transposed stores) with fused
//    edge filter (d2 < T, i < j) appending into g_ebuf[0].
// ---------------------------------------------------------------------------
#define KS 16
__global__ void __launch_bounds__(256) dist_kernel(const float* __restrict__ gts,
                                                   const float* __restrict__ z) {
    int bi = blockIdx.y, bj = blockIdx.x;
    if (bj < bi) return;
    int bm = blockIdx.z;
    const float* P = (bm < BATCH) ? gts + (size_t)bm * NPT * DIM
                                  : z + (size_t)(bm - BATCH) * NPT * DIM;
    int i0 = bi * 128, j0 = bj * 128;
    int tid = threadIdx.x;
    int tx = tid & 15;
    int ty = tid >> 4;
    int lane = tid & 31;

    __shared__ float As[KS][132];
    __shared__ float Bs[KS][132];

    float acc[8][8] = {};

    for (int ks = 0; ks < DIM; ks += KS) {
        __syncthreads();
#pragma unroll
        for (int t = 0; t < 2; t++) {
            int idx = tid + t * 256;
            int i = idx >> 2;
            int kk = (idx & 3) * 4;
            float4 va = *(const float4*)(P + (size_t)(i0 + i) * DIM + ks + kk);
            As[kk + 0][i] = va.x; As[kk + 1][i] = va.y;
            As[kk + 2][i] = va.z; As[kk + 3][i] = va.w;
            float4 vb = *(const float4*)(P + (size_t)(j0 + i) * DIM + ks + kk);
            Bs[kk + 0][i] = vb.x; Bs[kk + 1][i] = vb.y;
            Bs[kk + 2][i] = vb.z; Bs[kk + 3][i] = vb.w;
        }
        __syncthreads();
#pragma unroll
        for (int k = 0; k < KS; k++) {
            float a[8], b[8];
            *(float4*)(a)     = *(const float4*)&As[k][ty * 8];
            *(float4*)(a + 4) = *(const float4*)&As[k][ty * 8 + 4];
            *(float4*)(b)     = *(const float4*)&Bs[k][tx * 8];
            *(float4*)(b + 4) = *(const float4*)&Bs[k][tx * 8 + 4];
#pragma unroll
            for (int r = 0; r < 8; r++)
#pragma unroll
                for (int c = 0; c < 8; c++)
                    acc[r][c] += a[r] * b[c];
        }
    }

    const float* sqb = g_sq + bm * NPT;
    float sqi[8], sqj[8];
#pragma unroll
    for (int r = 0; r < 8; r++) sqi[r] = sqb[i0 + ty * 8 + r];
#pragma unroll
    for (int c = 0; c < 8; c++) sqj[c] = sqb[j0 + tx * 8 + c];

#pragma unroll
    for (int r = 0; r < 8; r++)
#pragma unroll
        for (int c = 0; c < 8; c++)
            acc[r][c] = fmaxf(sqi[r] + sqj[c] - 2.f * acc[r][c], 0.f);

    float* Dm = g_D + (size_t)bm * NPT * NPT;
#pragma unroll
    for (int r = 0; r < 8; r++) {
        int gi = i0 + ty * 8 + r;
        float4 o0 = {acc[r][0], acc[r][1], acc[r][2], acc[r][3]};
        float4 o1 = {acc[r][4], acc[r][5], acc[r][6], acc[r][7]};
        *(float4*)&Dm[(size_t)gi * NPT + j0 + tx * 8]     = o0;
        *(float4*)&Dm[(size_t)gi * NPT + j0 + tx * 8 + 4] = o1;
    }
    if (bi != bj) {
#pragma unroll
        for (int c = 0; c < 8; c++) {
            int gj = j0 + tx * 8 + c;
            float4 o0 = {acc[0][c], acc[1][c], acc[2][c], acc[3][c]};
            float4 o1 = {acc[4][c], acc[5][c], acc[6][c], acc[7][c]};
            *(float4*)&Dm[(size_t)gj * NPT + i0 + ty * 8]     = o0;
            *(float4*)&Dm[(size_t)gj * NPT + i0 + ty * 8 + 4] = o1;
        }
    }

    // ---- fused edge filter -> g_ebuf[0][bm] ----
    unsigned nl = 0;
#pragma unroll
    for (int r = 0; r < 8; r++) {
        int gi = i0 + ty * 8 + r;
#pragma unroll
        for (int c = 0; c < 8; c++) {
            int gj = j0 + tx * 8 + c;
            if (gi < gj && acc[r][c] < T_FILT) nl++;
        }
    }
    unsigned pre = nl;
#pragma unroll
    for (int o = 1; o < 32; o <<= 1) {
        unsigned v = __shfl_up_sync(0xFFFFFFFFu, pre, o);
        if (lane >= (int)o) pre += v;
    }
    unsigned wtot = __shfl_sync(0xFFFFFFFFu, pre, 31);
    unsigned ex = pre - nl;
    if (wtot) {
        unsigned base = 0;
        if (lane == 31) base = (unsigned)atomicAdd(&g_cnt[0][bm], (int)wtot);
        base = __shfl_sync(0xFFFFFFFFu, base, 31);
        if (base + wtot <= (unsigned)ECAP) {
            if (nl) {
                unsigned o = base + ex;
#pragma unroll
                for (int r = 0; r < 8; r++) {
                    int gi = i0 + ty * 8 + r;
#pragma unroll
                    for (int c = 0; c < 8; c++) {
                        int gj = j0 + tx * 8 + c;
                        if (gi < gj && acc[r][c] < T_FILT) {
                            g_ebuf[0][bm][o++] =
                                ((u64)__float_as_uint(acc[r][c]) << 22) |
                                ((unsigned)gi << 11) | (unsigned)gj;
                        }
                    }
                }
            }
        } else if (lane == 0) {
            g_ovf[bm] = 1;
        }
    }
}

// ---------------------------------------------------------------------------
// 3a. per-round edge scan: one THREAD per edge, grid-wide. Survivors (cross
//     edges) compact into the other parity buffer; best[comp] via
//     read-checked atomicMin (total-order keys -> deterministic result).
// ---------------------------------------------------------------------------
__global__ void __launch_bounds__(256) scan_kernel(int par) {
    int bm = blockIdx.y;
    if (g_ovf[bm] || g_nrec[bm] >= NPT - 1) return;
    int cnt = g_cnt[par][bm];
    if (cnt > ECAP) cnt = ECAP;
    const int lane = threadIdx.x & 31;

    for (int e = blockIdx.x * 256 + threadIdx.x; e < cnt; e += gridDim.x * 256) {
        u64 k = g_ebuf[par][bm][e];
        int i = (int)((k >> 11) & 2047), j = (int)(k & 2047);
        int ci = g_comp[bm][i], cj = g_comp[bm][j];
        bool keep = (ci != cj);

        unsigned ball = __ballot_sync(0xFFFFFFFFu, keep);
        if (ball) {
            int nkeep = __popc(ball);
            int rank = __popc(ball & ((1u << lane) - 1u));
            int base = 0;
            int leader = __ffs(ball) - 1;
            if (lane == leader) base = atomicAdd(&g_cnt[par ^ 1][bm], nkeep);
            base = __shfl_sync(0xFFFFFFFFu, base, leader);
            if (keep) {
                g_ebuf[par ^ 1][bm][base + rank] = k;
                if (k < g_best[bm][ci]) atomicMin(&g_best[bm][ci], k);
                if (k < g_best[bm][cj]) atomicMin(&g_best[bm][cj], k);
            }
        }
    }
}

// ---------------------------------------------------------------------------
// 3b. per-round hook/record/pointer-jump/relabel (one block per instance)
// ---------------------------------------------------------------------------
__global__ void __launch_bounds__(256) hook_kernel(int par) {
    __shared__ u64 sb[NPT];      // 16 KB
    __shared__ int scomp[NPT];   // 8 KB
    __shared__ int parr[NPT];    // 8 KB
    __shared__ int tmp[NPT];     // 8 KB
    __shared__ int cnt;

    int bm = blockIdx.x, tid = threadIdx.x;
    if (g_ovf[bm] || g_nrec[bm] >= NPT - 1) return;

    for (int i = tid; i < NPT; i += 256) {
        sb[i] = g_best[bm][i];
        scomp[i] = g_comp[bm][i];
    }
    if (tid == 0) { cnt = 0; g_cnt[par][bm] = 0; }  // consumed buffer reset
    __syncthreads();

    for (int c = tid; c < NPT; c += 256) {
        u64 k = sb[c];
        int p = c;
        if (k != ~0ull) {
            int a = (int)((k >> 11) & 2047), b = (int)(k & 2047);
            int ca = scomp[a], cb = scomp[b];
            p = (ca == c) ? cb : ca;
        }
        parr[c] = p;
    }
    __syncthreads();

    // 2-cycle fix (total-order keys => only mutual pairs; race-safe)
    for (int c = tid; c < NPT; c += 256) {
        int p = parr[c];
        if (p != c && parr[p] == c && c < p) parr[c] = c;
    }
    __syncthreads();

    for (int c = tid; c < NPT; c += 256) {
        if (parr[c] != c) {
            u64 k = sb[c];
            g_eroot[bm][c] = make_int2((int)((k >> 11) & 2047), (int)(k & 2047));
            atomicAdd(&cnt, 1);
        }
    }
    __syncthreads();

    for (int it = 0; it < 11; it++) {
        for (int c = tid; c < NPT; c += 256) tmp[c] = parr[parr[c]];
        __syncthreads();
        for (int c = tid; c < NPT; c += 256) parr[c] = tmp[c];
        __syncthreads();
    }

    for (int i = tid; i < NPT; i += 256) {
        g_comp[bm][i] = parr[scomp[i]];
        g_best[bm][i] = ~0ull;
    }
    if (tid == 0) atomicAdd(&g_nrec[bm], cnt);
}

// ---------------------------------------------------------------------------
// 3c. exact full-matrix fallback (no-op when sparse phase completed)
// ---------------------------------------------------------------------------
__global__ void __launch_bounds__(256) fallback_kernel() {
    __shared__ int comp[NPT];
    __shared__ int parent[NPT];
    __shared__ u64 best[NPT];
    __shared__ int s_rec;

    int bm = blockIdx.x;
    int tid = threadIdx.x;
    int lane = tid & 31, wid = tid >> 5;

    if (!g_ovf[bm] && g_nrec[bm] >= NPT - 1) return;

    for (int i = tid; i < NPT; i += 256) comp[i] = g_comp[bm][i];
    if (tid == 0) s_rec = g_nrec[bm];
    __syncthreads();

    const float* Dm = g_D + (size_t)bm * NPT * NPT;
    for (int round = 0; round < 12; round++) {
        if (s_rec >= NPT - 1) break;
        for (int i = tid; i < NPT; i += 256) best[i] = ~0ull;
        __syncthreads();

        for (int i = wid; i < NPT; i += 8) {
            int ci = comp[i];
            const float4* row = (const float4*)(Dm + (size_t)i * NPT);
            u64 lb = ~0ull;
            for (int jc = lane; jc < NPT / 4; jc += 32) {
                float4 d4 = row[jc];
                float dv[4] = {d4.x, d4.y, d4.z, d4.w};
#pragma unroll
                for (int q = 0; q < 4; q++) {
                    int j = jc * 4 + q;
                    if (comp[j] != ci) {
                        int lo = i < j ? i : j, hi = i < j ? j : i;
                        u64 k = ((u64)__float_as_uint(dv[q]) << 22) |
                                ((unsigned)lo << 11) | (unsigned)hi;
                        if (k < lb) lb = k;
                    }
                }
            }
#pragma unroll
            for (int o = 16; o; o >>= 1) {
                u64 v = __shfl_down_sync(0xFFFFFFFFu, lb, o);
                if (v < lb) lb = v;
            }
            if (lane == 0 && lb != ~0ull) atomicMin(&best[ci], lb);
        }
        __syncthreads();

        for (int c = tid; c < NPT; c += 256) {
            u64 k = best[c];
            int p = c;
            if (k != ~0ull) {
                int i = (int)((k >> 11) & 2047), j = (int)(k & 2047);
                int ci = comp[i], cj = comp[j];
                p = (ci == c) ? cj : ci;
            }
            parent[c] = p;
        }
        __syncthreads();
        for (int c = tid; c < NPT; c += 256) {
            int p = parent[c];
            if (p != c && parent[p] == c && c < p) parent[c] = c;
        }
        __syncthreads();
        for (int c = tid; c < NPT; c += 256) {
            if (parent[c] != c) {
                u64 k = best[c];
                g_eroot[bm][c] = make_int2((int)((k >> 11) & 2047), (int)(k & 2047));
                atomicAdd(&s_rec, 1);
            }
        }
        __syncthreads();
        int* tmp = (int*)best;
        for (int it = 0; it < 11; it++) {
            for (int c = tid; c < NPT; c += 256) tmp[c] = parent[parent[c]];
            __syncthreads();
            for (int c = tid; c < NPT; c += 256) parent[c] = tmp[c];
            __syncthreads();
        }
        for (int i = tid; i < NPT; i += 256) comp[i] = parent[comp[i]];
        __syncthreads();
    }
}

// ---------------------------------------------------------------------------
// 4. loss
// ---------------------------------------------------------------------------
__global__ void loss_kernel() {
    int bm = blockIdx.x;
    int b = bm & (BATCH - 1);
    const float* Dx = g_D + (size_t)b * NPT * NPT;
    const float* Dz = g_D + (size_t)(BATCH + b) * NPT * NPT;

    float acc = 0.f;
    for (int s = threadIdx.x; s < NPT; s += 256) {
        int2 p = g_eroot[bm][s];
        if (p.x >= 0) {
            float dx = sqrtf(Dx[(size_t)p.x * NPT + p.y]);
            float dz = sqrtf(Dz[(size_t)p.x * NPT + p.y]);
            float t = dx - dz;
            acc += t * t;
        }
    }
    __shared__ float sm[256];
    sm[threadIdx.x] = acc;
    __syncthreads();
    for (int s = 128; s; s >>= 1) {
        if (threadIdx.x < s) sm[threadIdx.x] += sm[threadIdx.x + s];
        __syncthreads();
    }
    if (threadIdx.x == 0) g_partial[bm] = sm[0];
}

__global__ void final_kernel(float* out) {
    if (threadIdx.x == 0) {
        float s = 0.f;
        for (int i = 0; i < NMAT; i++) s += g_partial[i];
        out[0] = 0.5f * s;
    }
}

// ---------------------------------------------------------------------------
extern "C" void kernel_launch(void* const* d_in, const int* in_sizes, int n_in,
                              void* d_out, int out_size) {
    (void)in_sizes; (void)n_in; (void)out_size;
    const float* gts = (const float*)d_in[0];
    const float* z   = (const float*)d_in[1];

    norms_kernel<<<NMAT * NPT / 256, 256>>>(gts, z);

    dim3 g(NPT / 128, NPT / 128, NMAT);
    dist_kernel<<<g, 256>>>(gts, z);

    for (int r = 0; r < NROUNDS; r++) {
        scan_kernel<<<dim3(96, NMAT), 256>>>(r & 1);
        hook_kernel<<<NMAT, 256>>>(r & 1);
    }
    fallback_kernel<<<NMAT, 256>>>();

    loss_kernel<<<NMAT, 256>>>();
    final_kernel<<<1, 32>>>((float*)d_out);
}